// round 15
// baseline (speedup 1.0000x reference)
#include <cuda_runtime.h>
#include <math.h>

// Problem constants (fixed shapes per reference)
#define BDIM    512
#define DEG     16
#define NSLOT   17
#define NREAD   22
#define NEGK    5
#define H       256
#define NNODES  200000
#define HBITS   15
#define HSIZE   (1 << HBITS)
#define HMASK   (HSIZE - 1)
#define HK      16
#define CPR     256
#define NCHUNK  ((NNODES + CPR - 1) / CPR)     // 782
#define TOTAL_WORK (BDIM + NCHUNK + BDIM)      // steps, copies, post tasks
#define NTHR    256
#define FULLMASK 0x1FFFF
#define TILE    16384                           // TMA copy tile (bytes)
#define NBUF    5
#define DSMEM   (NBUF * TILE)                   // 80KB copy buffers

// ------------------------- persistent device state -------------------------
__device__ __align__(16) float g_staging[BDIM][NSLOT][H];   // 8.9 MB
// Blocked-transposed weights: g_BT[m][i4*H + h] = float4(W_m[h][4*i4..])
// m: 0=Wh, 1=We2n, 2=Wre, 3=Wrn
__device__ __align__(16) float4 g_BT[4][(H / 4) * H];       // 1 MB
__device__ int g_done[BDIM];           // bitmask of completed slots
__device__ int g_needed[BDIM];         // slots some future step reads
__device__ int g_src[BDIM][NREAD];     // -1 => z0[row], else (t'<<5)|w'
__device__ int g_ctr;
__device__ int g_copy_cnt;             // completed copy chunks
__device__ int g_hrow[HSIZE];
__device__ int g_hcnt[HSIZE];
__device__ int g_hent[HSIZE][HK];      // e = (t<<10)|(prio<<5)|w

// ------------------------------- helpers -----------------------------------
__device__ __forceinline__ unsigned hashrow(int row) {
    return ((unsigned)row * 2654435761u) >> (32 - HBITS);
}
__device__ __forceinline__ int ld_acq(const int* p) {
    int v; asm volatile("ld.acquire.gpu.b32 %0, [%1];" : "=r"(v) : "l"(p) : "memory"); return v;
}
// Two-level spin: tight poll first (fast detect), then nanosleep backoff.
__device__ __forceinline__ void wait_bit(int* flag, int bit) {
    #pragma unroll 1
    for (int k = 0; k < 96; ++k) if (ld_acq(flag) & bit) return;
    while (!(ld_acq(flag) & bit)) __nanosleep(32);
}
__device__ __forceinline__ void red_or_rel(int* p, int v) {
    asm volatile("red.release.gpu.global.or.b32 [%0], %1;" :: "l"(p), "r"(v) : "memory");
}
__device__ __forceinline__ void red_add_rel(int* p, int v) {
    asm volatile("red.release.gpu.global.add.s32 [%0], %1;" :: "l"(p), "r"(v) : "memory");
}
__device__ __forceinline__ void prefetch_l2(const void* p) {
    asm volatile("prefetch.global.L2 [%0];" :: "l"(p));
}
__device__ __forceinline__ void upk2(unsigned long long v, float& lo, float& hi) {
    asm("mov.b64 {%0, %1}, %2;" : "=f"(lo), "=f"(hi) : "l"(v));
}
__device__ __forceinline__ void fma2(unsigned long long& d, unsigned long long a, unsigned long long b) {
    asm("fma.rn.f32x2 %0, %1, %2, %0;" : "+l"(d) : "l"(a), "l"(b));
}
__device__ __forceinline__ float sigmoidf_(float x) { return 1.0f / (1.0f + expf(-x)); }

// ---- TMA bulk copy primitives ----
__device__ __forceinline__ void mbar_init(unsigned a, unsigned cnt) {
    asm volatile("mbarrier.init.shared.b64 [%0], %1;" :: "r"(a), "r"(cnt) : "memory");
}
__device__ __forceinline__ void mbar_expect(unsigned a, unsigned bytes) {
    asm volatile("mbarrier.arrive.expect_tx.shared.b64 _, [%0], %1;" :: "r"(a), "r"(bytes) : "memory");
}
__device__ __forceinline__ void mbar_wait(unsigned a, unsigned ph) {
    asm volatile(
        "{\n\t.reg .pred P;\n\t"
        "W%=:\n\t"
        "mbarrier.try_wait.parity.shared.b64 P, [%0], %1;\n\t"
        "@!P bra W%=;\n\t}"
        :: "r"(a), "r"(ph) : "memory");
}
__device__ __forceinline__ void bulk_g2s(unsigned saddr, const void* g, unsigned bytes, unsigned mbar) {
    asm volatile("cp.async.bulk.shared::cta.global.mbarrier::complete_tx::bytes [%0], [%1], %2, [%3];"
        :: "r"(saddr), "l"(g), "r"(bytes), "r"(mbar) : "memory");
}
__device__ __forceinline__ void bulk_s2g(void* g, unsigned saddr, unsigned bytes) {
    asm volatile("cp.async.bulk.global.shared::cta.bulk_group [%0], [%1], %2;"
        :: "l"(g), "r"(saddr), "r"(bytes) : "memory");
}
__device__ __forceinline__ void bulk_commit() {
    asm volatile("cp.async.bulk.commit_group;" ::: "memory");
}
template <int N>
__device__ __forceinline__ void bulk_wait() {
    asm volatile("cp.async.bulk.wait_group %0;" :: "n"(N) : "memory");
}

// Coalesced matvec via blocked-transposed weights; vec from smem.
__device__ __forceinline__ float matvec_bt(const ulonglong2* __restrict__ BT2, int h,
                                           const float* __restrict__ vec) {
    const ulonglong2* v = (const ulonglong2*)vec;
    unsigned long long acc = 0ull;
    #pragma unroll
    for (int b = 0; b < 4; ++b) {
        ulonglong2 w[16];
        #pragma unroll
        for (int i = 0; i < 16; ++i) w[i] = BT2[(b * 16 + i) * H + h];
        #pragma unroll
        for (int i = 0; i < 16; ++i) {
            fma2(acc, w[i].x, v[b * 16 + i].x);
            fma2(acc, w[i].y, v[b * 16 + i].y);
        }
    }
    float lo, hi; upk2(acc, lo, hi);
    return lo + hi;
}

// Fused dual matvec: two weight streams interleaved (overlapped latency).
__device__ __forceinline__ float2 matvec2_bt(const ulonglong2* __restrict__ BTa,
                                             const float* __restrict__ va,
                                             const ulonglong2* __restrict__ BTb,
                                             const float* __restrict__ vb, int h) {
    const ulonglong2* A = (const ulonglong2*)va;
    const ulonglong2* B = (const ulonglong2*)vb;
    unsigned long long accA = 0ull, accB = 0ull;
    #pragma unroll
    for (int bb = 0; bb < 8; ++bb) {
        ulonglong2 wa[8], wb[8];
        #pragma unroll
        for (int i = 0; i < 8; ++i) wa[i] = BTa[(bb * 8 + i) * H + h];
        #pragma unroll
        for (int i = 0; i < 8; ++i) wb[i] = BTb[(bb * 8 + i) * H + h];
        #pragma unroll
        for (int i = 0; i < 8; ++i) {
            fma2(accA, wa[i].x, A[bb * 8 + i].x); fma2(accA, wa[i].y, A[bb * 8 + i].y);
            fma2(accB, wb[i].x, B[bb * 8 + i].x); fma2(accB, wb[i].y, B[bb * 8 + i].y);
        }
    }
    float a0, a1, b0, b1; upk2(accA, a0, a1); upk2(accB, b0, b1);
    return make_float2(a0 + a1, b0 + b1);
}

// ------------------------------- kernels -----------------------------------
// Merged clear + weight transpose. 65536 threads.
__global__ void k_prep(const float* __restrict__ Wh,  const float* __restrict__ We2n,
                       const float* __restrict__ Wre, const float* __restrict__ Wrn) {
    int idx = blockIdx.x * blockDim.x + threadIdx.x;
    if (idx < HSIZE) { g_hrow[idx] = -1; g_hcnt[idx] = 0; }
    if (idx < BDIM) { g_done[idx] = 0; g_needed[idx] = 0; }
    if (idx == 0) { g_ctr = 0; g_copy_cnt = 0; }
    int m = idx >> 14, rem = idx & 16383;
    int i4 = rem >> 8, h = rem & 255;
    const float* W = (m == 0) ? Wh : (m == 1) ? We2n : (m == 2) ? Wre : Wrn;
    g_BT[m][i4 * H + h] = *(const float4*)(W + (size_t)h * H + i4 * 4);
}

__global__ void k_insert(const int* __restrict__ u) {
    int idx = blockIdx.x * blockDim.x + threadIdx.x;
    if (idx >= BDIM * NSLOT) return;
    int t = idx / NSLOT, w = idx % NSLOT;
    int row = u[t * NSLOT + w];
    int prio = (w == 0) ? 16 : (w - 1);            // event applied last; later neighbor wins
    int e = (t << 10) | (prio << 5) | w;
    unsigned hsh = hashrow(row);
    for (;;) {
        int cur = atomicCAS(&g_hrow[hsh], -1, row);
        if (cur == -1 || cur == row) {
            int c = atomicAdd(&g_hcnt[hsh], 1);
            if (c < HK) g_hent[hsh][c] = e;
            break;
        }
        hsh = (hsh + 1) & HMASK;
    }
}

__global__ void k_resolve(const int* __restrict__ u, const int* __restrict__ u_neg,
                          const float* __restrict__ z0, const float* __restrict__ time_bar,
                          const float* __restrict__ td) {
    int idx = blockIdx.x * blockDim.x + threadIdx.x;
    if (idx < 1088) prefetch_l2(td + idx * 32);    // whole td array
    if (idx >= BDIM * NREAD) return;
    int t = idx / NREAD, r = idx % NREAD;
    int row = (r < NSLOT) ? u[t * NSLOT + r] : u_neg[t * NEGK + (r - NSLOT)];
    if (r >= NSLOT) prefetch_l2(time_bar + (size_t)t * NNODES + row);
    unsigned hsh = hashrow(row);
    int src = -1, bestkey = -1;
    for (;;) {
        int cur = g_hrow[hsh];
        if (cur == -1) break;
        if (cur == row) {
            int c = g_hcnt[hsh]; if (c > HK) c = HK;
            for (int i = 0; i < c; ++i) {
                int e = g_hent[hsh][i];
                if ((e >> 10) < t) {
                    int key = e >> 5;
                    if (key > bestkey) { bestkey = key; src = ((e >> 10) << 5) | (e & 31); }
                }
            }
            break;
        }
        hsh = (hsh + 1) & HMASK;
    }
    g_src[t][r] = src;
    if (src >= 0) {
        if (r < NSLOT) atomicOr(&g_needed[src >> 5], 1 << (src & 31));
    } else {
        const float* p = z0 + (size_t)row * H;     // prefetch the z0 row
        #pragma unroll
        for (int l = 0; l < 8; ++l) prefetch_l2(p + l * 32);
    }
}

// Persistent main kernel: 256 threads/CTA, 2 CTAs/SM, single work counter.
// ids [0,512): solo steps. [512,1294): deep TMA copy chunks.
// ids [1294,1806): post tasks (Hawkes lambdas + final row scatter per step).
__global__ void __launch_bounds__(NTHR, 2) k_main(
    const int* __restrict__ u, const float* __restrict__ td,
    const float* __restrict__ time_bar, const float* __restrict__ time_cur,
    const int* __restrict__ u_neg, const float* __restrict__ z0,
    const float* __restrict__ bh,  const float* __restrict__ be2n,
    const float* __restrict__ bre, const float* __restrict__ brn,
    const float* __restrict__ Wt,  const float* __restrict__ bt,
    const float* __restrict__ Wom, const float* __restrict__ bom_p,
    const float* __restrict__ wt_p, const float* __restrict__ alpha_p,
    const float* __restrict__ psi_p, float* __restrict__ out)
{
    __shared__ __align__(16) float s_znb[DEG][H];
    __shared__ __align__(16) float s_emb[H];
    __shared__ __align__(16) float s_mean[H];
    __shared__ float s_td[NSLOT][4];
    __shared__ __align__(8) unsigned long long s_mbar[NBUF];
    __shared__ int s_id;
    extern __shared__ __align__(16) char s_buf[];        // NBUF x 16KB copy buffers

    const int tid  = threadIdx.x;              // == h (output column)
    const int lane = tid & 31, wid = tid >> 5;
    float* outz = out + (BDIM + BDIM * NEGK);
    char* outzb = (char*)outz;
    const ulonglong2* BT_h   = (const ulonglong2*)g_BT[0];
    const ulonglong2* BT_e2n = (const ulonglong2*)g_BT[1];
    const ulonglong2* BT_re  = (const ulonglong2*)g_BT[2];
    const ulonglong2* BT_rn  = (const ulonglong2*)g_BT[3];
    const float inv_sd[4] = {1.f/50.f, 1.f/7.f, 1.f/15.f, 1.f/15.f};

    // TMA copy state (only tid 0 uses)
    unsigned mb[NBUF], sb[NBUF];
    unsigned ph[NBUF] = {0, 0, 0, 0, 0};
    #pragma unroll
    for (int i = 0; i < NBUF; ++i) {
        mb[i] = (unsigned)__cvta_generic_to_shared(&s_mbar[i]);
        sb[i] = (unsigned)__cvta_generic_to_shared(s_buf) + i * TILE;
    }
    if (tid == 0) {
        #pragma unroll
        for (int i = 0; i < NBUF; ++i) mbar_init(mb[i], 1);
    }

    for (;;) {
        __syncthreads();                      // protect s_id / smem; orders mbar init
        if (tid == 0) s_id = atomicAdd(&g_ctr, 1);
        __syncthreads();
        const int id = s_id;
        if (id >= TOTAL_WORK) break;

        // =================== DEEP TMA COPY CHUNK ===================
        if (id >= BDIM && id < BDIM + NCHUNK) {
            if (tid == 0) {
                int chunk = id - BDIM;
                size_t byte0 = (size_t)chunk * CPR * H * 4;
                size_t total = (size_t)NNODES * H * 4;
                unsigned nb = (unsigned)(((total - byte0) < (size_t)(CPR * H * 4))
                                         ? (total - byte0) : (size_t)(CPR * H * 4));
                const char* src = (const char*)z0 + byte0;
                char*       dst = outzb + byte0;
                unsigned ntile = (nb + TILE - 1) / TILE;   // 16 (last chunk: 2)
                for (unsigned i = 0; i < ntile && i < 3; ++i) {
                    unsigned b = i % NBUF;
                    unsigned tb = ((i + 1) * TILE <= nb) ? TILE : (nb - i * TILE);
                    mbar_expect(mb[b], tb);
                    bulk_g2s(sb[b], src + i * TILE, tb, mb[b]);
                }
                for (unsigned i = 0; i < ntile; ++i) {
                    unsigned b = i % NBUF;
                    unsigned tb = ((i + 1) * TILE <= nb) ? TILE : (nb - i * TILE);
                    mbar_wait(mb[b], ph[b]); ph[b] ^= 1;
                    bulk_s2g(dst + i * TILE, sb[b], tb);
                    bulk_commit();
                    bulk_wait<2>();               // stores <= i-2 complete
                    if (i + 3 < ntile) {
                        unsigned b2 = (i + 3) % NBUF;
                        unsigned t2 = ((i + 4) * TILE <= nb) ? TILE : (nb - (i + 3) * TILE);
                        mbar_expect(mb[b2], t2);
                        bulk_g2s(sb[b2], src + (i + 3) * TILE, t2, mb[b2]);
                    }
                }
                bulk_wait<0>();                   // drain before buffers reused
                red_add_rel(&g_copy_cnt, 1);
            }
            continue;
        }

        // =================== POST TASK (lambdas + scatter) ===================
        if (id >= BDIM + NCHUNK) {
            const int s = id - (BDIM + NCHUNK);
            if (tid < 6) {                        // wait for lambda sources
                int r = (tid < 5) ? (NSLOT + tid) : 0;
                int sv = g_src[s][r];
                if (sv >= 0) wait_bit(&g_done[sv >> 5], 1 << (sv & 31));
            }
            __syncthreads();
            const float w_t = *wt_p, alpha = *alpha_p, psi = *psi_p, bom = *bom_p;
            const float inv_psi = 1.0f / (psi + 1e-7f);
            if (wid < NEGK) {                     // negative lambdas
                int node = u_neg[s * NEGK + wid];
                int sv = g_src[s][NSLOT + wid];
                const float* srcp = (sv >= 0) ? g_staging[sv >> 5][sv & 31]
                                              : (z0 + (size_t)node * H);
                float acc = 0.f;
                for (int i = lane; i < H; i += 32) acc += srcp[i] * Wom[i];
                #pragma unroll
                for (int o = 16; o; o >>= 1) acc += __shfl_down_sync(0xffffffffu, acc, o);
                if (lane == 0) {
                    float ts = time_cur[s] - time_bar[(size_t)s * NNODES + node];
                    float g = acc + bom + alpha * expf(-w_t * (ts * (1.0f / 86400.0f)));
                    float gp = fminf(fmaxf(g * inv_psi, -75.f), 75.f);
                    out[BDIM + s * NEGK + wid] = psi * log1pf(expf(gp)) * (1.0f / NEGK);
                }
            } else if (wid == 5) {                // positive lambda
                int sv = g_src[s][0];
                const float* srcp = (sv >= 0) ? g_staging[sv >> 5][sv & 31]
                                              : (z0 + (size_t)u[s * NSLOT] * H);
                float acc = 0.f;
                for (int i = lane; i < H; i += 32) acc += srcp[i] * Wom[i];
                #pragma unroll
                for (int o = 16; o; o >>= 1) acc += __shfl_down_sync(0xffffffffu, acc, o);
                if (lane == 0) {
                    float ts = time_cur[s] - td[s * NSLOT * 4] * (1.0f / 50.0f);
                    float g = acc + bom + alpha * expf(-w_t * (ts * (1.0f / 86400.0f)));
                    float gp = fminf(fmaxf(g * inv_psi, -75.f), 75.f);
                    out[s] = psi * log1pf(expf(gp));
                }
            }
            // scatter needs: this step's staging final + all copy chunks done
            if (tid == 0) {
                while (ld_acq(&g_done[s]) != FULLMASK) __nanosleep(32);
                while (ld_acq(&g_copy_cnt) < NCHUNK) __nanosleep(64);
            }
            __syncthreads();
            for (int w = wid; w < NSLOT; w += 8) {
                int row = u[s * NSLOT + w];
                unsigned hsh = hashrow(row);
                int beste = -1, bestkey = -1;
                for (;;) {
                    int cur = g_hrow[hsh];
                    if (cur == -1) break;
                    if (cur == row) {
                        int c = g_hcnt[hsh]; if (c > HK) c = HK;
                        for (int i = 0; i < c; ++i) {
                            int e = g_hent[hsh][i];
                            int key = e >> 5;
                            if (key > bestkey) { bestkey = key; beste = e; }
                        }
                        break;
                    }
                    hsh = (hsh + 1) & HMASK;
                }
                int prio = (w == 0) ? 16 : (w - 1);
                if (beste == ((s << 10) | (prio << 5) | w)) {   // (s,w) is last writer
                    const float4* src = (const float4*)g_staging[s][w];
                    float4* dst = (float4*)outz + (size_t)row * (H / 4);
                    dst[lane]      = src[lane];
                    dst[lane + 32] = src[lane + 32];
                }
            }
            continue;
        }

        // =================== STEP s ===================
        const int s = id;

        // ---- Phase 0: warp 0 waits on dependent slots; warps 1..7 load
        //      independent (z0-sourced) rows concurrently ----
        if (wid == 0) {
            if (lane < NSLOT) {
                int sv = g_src[s][lane];
                if (sv >= 0) wait_bit(&g_done[sv >> 5], 1 << (sv & 31));
            }
        } else {
            for (int r = wid - 1; r < NSLOT; r += 7) {
                int sv = g_src[s][r];
                if (sv < 0) {
                    const float4* src4 = (const float4*)(z0 + (size_t)u[s * NSLOT + r] * H);
                    float4* dst4 = (r == 0) ? (float4*)s_emb : (float4*)s_znb[r - 1];
                    dst4[lane]      = src4[lane];
                    dst4[lane + 32] = src4[lane + 32];
                }
            }
        }
        __syncthreads();

        // ---- Phase 0b: load dependent rows (usually 0-2) + time deltas ----
        for (int r = wid; r < NSLOT; r += 8) {
            int sv = g_src[s][r];
            if (sv >= 0) {
                const float4* src4 = (const float4*)g_staging[sv >> 5][sv & 31];
                float4* dst4 = (r == 0) ? (float4*)s_emb : (float4*)s_znb[r - 1];
                dst4[lane]      = src4[lane];
                dst4[lane + 32] = src4[lane + 32];
            }
        }
        if (tid >= 188) {                       // 68 threads load 68 td values
            int q = tid - 188;
            s_td[q >> 2][q & 3] = td[(s * NSLOT + (q >> 2)) * 4 + (q & 3)] * inv_sd[q & 3];
        }
        __syncthreads();

        const int h = tid;
        const int need = g_needed[s];
        const int nneed = (need >> 1) & 0xFFFF;    // needed neighbor slots
        float4 wtr = *(const float4*)(Wt + (size_t)h * 4);
        float btv = bt[h];

        // ---- Phase 1a: cmn fused with first needed neighbor; publish ASAP ----
        float cmn;
        if (nneed) {
            int j0 = __ffs(nneed) - 1;
            float2 r2 = matvec2_bt(BT_e2n, s_emb, BT_rn, s_znb[j0], h);
            cmn = r2.x + be2n[h] + brn[h];
            {
                float tf = btv + wtr.x*s_td[1+j0][0] + wtr.y*s_td[1+j0][1]
                               + wtr.z*s_td[1+j0][2] + wtr.w*s_td[1+j0][3];
                g_staging[s][1 + j0][h] = sigmoidf_(r2.y + cmn + tf);
            }
            for (int m = nneed & (nneed - 1); m; m &= (m - 1)) {
                int j = __ffs(m) - 1;
                float d = matvec_bt(BT_rn, h, s_znb[j]);
                float tf = btv + wtr.x*s_td[1+j][0] + wtr.y*s_td[1+j][1]
                               + wtr.z*s_td[1+j][2] + wtr.w*s_td[1+j][3];
                g_staging[s][1 + j][h] = sigmoidf_(d + cmn + tf);
            }
            __syncthreads();
            if (tid == 0) red_or_rel(&g_done[s], nneed << 1);
        } else {
            cmn = matvec_bt(BT_e2n, h, s_emb) + be2n[h] + brn[h];
        }

        // ---- mean over 16 neighbor rows (only z_ev needs it) ----
        {
            float acc = 0.f;
            #pragma unroll
            for (int j = 0; j < DEG; ++j) acc += s_znb[j][tid];
            s_mean[tid] = acc * (1.0f / DEG);
        }
        __syncthreads();

        // ---- Phase 1b: z_ev (fused dual matvec); publish early iff read ----
        {
            float2 r2 = matvec2_bt(BT_h, s_mean, BT_re, s_emb, h);
            float tf0 = btv + wtr.x*s_td[0][0] + wtr.y*s_td[0][1]
                            + wtr.z*s_td[0][2] + wtr.w*s_td[0][3];
            g_staging[s][0][h] = sigmoidf_(r2.x + bh[h] + r2.y + bre[h] + tf0);
            if (need & 1) {
                __syncthreads();
                if (tid == 0) red_or_rel(&g_done[s], 1);
            }
        }

        // ---- Phase 2: remaining neighbor slots (GEMM, 4-deep weight prefetch) ----
        {
            unsigned long long acc2[DEG];
            #pragma unroll
            for (int j = 0; j < DEG; ++j) acc2[j] = 0ull;
            ulonglong2 wb[4];
            #pragma unroll
            for (int p = 0; p < 4; ++p) wb[p] = BT_rn[p * H + h];
            for (int i4 = 0; i4 < H / 4; i4 += 4) {
                ulonglong2 w0 = wb[0], w1 = wb[1], w2 = wb[2], w3 = wb[3];
                if (i4 + 4 < H / 4) {
                    #pragma unroll
                    for (int p = 0; p < 4; ++p) wb[p] = BT_rn[(i4 + 4 + p) * H + h];
                }
                #pragma unroll
                for (int j = 0; j < DEG; ++j) {
                    ulonglong2 z0v = *(const ulonglong2*)&s_znb[j][i4 * 4];
                    fma2(acc2[j], w0.x, z0v.x); fma2(acc2[j], w0.y, z0v.y);
                    ulonglong2 z1v = *(const ulonglong2*)&s_znb[j][(i4 + 1) * 4];
                    fma2(acc2[j], w1.x, z1v.x); fma2(acc2[j], w1.y, z1v.y);
                    ulonglong2 z2v = *(const ulonglong2*)&s_znb[j][(i4 + 2) * 4];
                    fma2(acc2[j], w2.x, z2v.x); fma2(acc2[j], w2.y, z2v.y);
                    ulonglong2 z3v = *(const ulonglong2*)&s_znb[j][(i4 + 3) * 4];
                    fma2(acc2[j], w3.x, z3v.x); fma2(acc2[j], w3.y, z3v.y);
                }
            }
            #pragma unroll
            for (int j = 0; j < DEG; ++j) {
                if (!((nneed >> j) & 1)) {
                    float lo, hi; upk2(acc2[j], lo, hi);
                    float tf = btv + wtr.x*s_td[1+j][0] + wtr.y*s_td[1+j][1]
                                   + wtr.z*s_td[1+j][2] + wtr.w*s_td[1+j][3];
                    g_staging[s][1 + j][h] = sigmoidf_(lo + hi + cmn + tf);
                }
            }
        }
        __syncthreads();
        if (tid == 0) red_or_rel(&g_done[s], FULLMASK);
    }
}

// ------------------------------- launch ------------------------------------
extern "C" void kernel_launch(void* const* d_in, const int* in_sizes, int n_in,
                              void* d_out, int out_size) {
    const int*   u     = (const int*)  d_in[0];
    const float* td    = (const float*)d_in[1];
    const float* tbar  = (const float*)d_in[2];
    const float* tcur  = (const float*)d_in[3];
    // d_in[4] significance, d_in[5] magnitudo: unused by reference
    const int*   uneg  = (const int*)  d_in[6];
    const float* z0    = (const float*)d_in[7];
    const float* Wh    = (const float*)d_in[8];
    const float* bh    = (const float*)d_in[9];
    const float* We2n  = (const float*)d_in[10];
    const float* be2n  = (const float*)d_in[11];
    const float* Wre   = (const float*)d_in[12];
    const float* bre   = (const float*)d_in[13];
    const float* Wrn   = (const float*)d_in[14];
    const float* brn   = (const float*)d_in[15];
    const float* Wt    = (const float*)d_in[16];
    const float* bt    = (const float*)d_in[17];
    const float* Wom   = (const float*)d_in[18];
    const float* bom   = (const float*)d_in[19];
    const float* wt    = (const float*)d_in[20];
    const float* alpha = (const float*)d_in[21];
    const float* psi   = (const float*)d_in[22];
    float* out = (float*)d_out;

    static int attr_set = 0;
    if (!attr_set) {
        cudaFuncSetAttribute(k_main, cudaFuncAttributeMaxDynamicSharedMemorySize, DSMEM);
        attr_set = 1;
    }

    k_prep   <<<256, 256>>>(Wh, We2n, Wre, Wrn);
    k_insert <<<(BDIM * NSLOT + 255) / 256, 256>>>(u);
    k_resolve<<<(BDIM * NREAD + 255) / 256, 256>>>(u, uneg, z0, tbar, td);

    int dev = 0, nsm = 148;
    cudaGetDevice(&dev);
    cudaDeviceGetAttribute(&nsm, cudaDevAttrMultiProcessorCount, dev);

    k_main<<<nsm * 2, NTHR, DSMEM>>>(u, td, tbar, tcur, uneg, z0,
                                     bh, be2n, bre, brn, Wt, bt,
                                     Wom, bom, wt, alpha, psi, out);
}

// round 16
// speedup vs baseline: 1.1148x; 1.1148x over previous
#include <cuda_runtime.h>
#include <math.h>

// Problem constants (fixed shapes per reference)
#define BDIM    512
#define DEG     16
#define NSLOT   17
#define NREAD   22
#define NEGK    5
#define H       256
#define NNODES  200000
#define HBITS   15
#define HSIZE   (1 << HBITS)
#define HMASK   (HSIZE - 1)
#define HK      16
#define CPR     256
#define NCHUNK  ((NNODES + CPR - 1) / CPR)     // 782
#define TOTAL_WORK (BDIM + NCHUNK)             // steps first, then copies
#define NTHR    256
#define FULLMASK 0x1FFFF
#define TILE    6144                            // copy tile bytes (per stream)
#define NSTREAM 4                               // parallel TMA streams per CTA
#define NBUFS   3                               // buffers per stream
#define DSMEM   (NSTREAM * NBUFS * TILE)        // 72KB copy buffers

// ------------------------- persistent device state -------------------------
__device__ __align__(16) float g_staging[BDIM][NSLOT][H];   // 8.9 MB
// Blocked-transposed weights: g_BT[m][i4*H + h] = float4(W_m[h][4*i4..])
// m: 0=Wh, 1=We2n, 2=Wre, 3=Wrn
__device__ __align__(16) float4 g_BT[4][(H / 4) * H];       // 1 MB
__device__ int g_done[BDIM];           // bitmask of completed slots
__device__ int g_needed[BDIM];         // slots some future step reads
__device__ int g_src[BDIM][NREAD];     // -1 => z0[row], else (t'<<5)|w'
__device__ int g_ctr;
__device__ int g_hrow[HSIZE];
__device__ int g_hcnt[HSIZE];
__device__ int g_hent[HSIZE][HK];      // e = (t<<10)|(prio<<5)|w

// ------------------------------- helpers -----------------------------------
__device__ __forceinline__ unsigned hashrow(int row) {
    return ((unsigned)row * 2654435761u) >> (32 - HBITS);
}
__device__ __forceinline__ int ld_acq(const int* p) {
    int v; asm volatile("ld.acquire.gpu.b32 %0, [%1];" : "=r"(v) : "l"(p) : "memory"); return v;
}
// Two-level spin: tight poll first (fast detect), then nanosleep backoff.
__device__ __forceinline__ void wait_bit(int* flag, int bit) {
    #pragma unroll 1
    for (int k = 0; k < 96; ++k) if (ld_acq(flag) & bit) return;
    while (!(ld_acq(flag) & bit)) __nanosleep(32);
}
__device__ __forceinline__ void red_or_rel(int* p, int v) {
    asm volatile("red.release.gpu.global.or.b32 [%0], %1;" :: "l"(p), "r"(v) : "memory");
}
__device__ __forceinline__ void prefetch_l2(const void* p) {
    asm volatile("prefetch.global.L2 [%0];" :: "l"(p));
}
__device__ __forceinline__ void upk2(unsigned long long v, float& lo, float& hi) {
    asm("mov.b64 {%0, %1}, %2;" : "=f"(lo), "=f"(hi) : "l"(v));
}
__device__ __forceinline__ void fma2(unsigned long long& d, unsigned long long a, unsigned long long b) {
    asm("fma.rn.f32x2 %0, %1, %2, %0;" : "+l"(d) : "l"(a), "l"(b));
}
__device__ __forceinline__ float sigmoidf_(float x) { return 1.0f / (1.0f + expf(-x)); }

// ---- TMA bulk copy primitives ----
__device__ __forceinline__ void mbar_init(unsigned a, unsigned cnt) {
    asm volatile("mbarrier.init.shared.b64 [%0], %1;" :: "r"(a), "r"(cnt) : "memory");
}
__device__ __forceinline__ void mbar_expect(unsigned a, unsigned bytes) {
    asm volatile("mbarrier.arrive.expect_tx.shared.b64 _, [%0], %1;" :: "r"(a), "r"(bytes) : "memory");
}
__device__ __forceinline__ void mbar_wait(unsigned a, unsigned ph) {
    asm volatile(
        "{\n\t.reg .pred P;\n\t"
        "W%=:\n\t"
        "mbarrier.try_wait.parity.shared.b64 P, [%0], %1;\n\t"
        "@!P bra W%=;\n\t}"
        :: "r"(a), "r"(ph) : "memory");
}
__device__ __forceinline__ void bulk_g2s(unsigned saddr, const void* g, unsigned bytes, unsigned mbar) {
    asm volatile("cp.async.bulk.shared::cta.global.mbarrier::complete_tx::bytes [%0], [%1], %2, [%3];"
        :: "r"(saddr), "l"(g), "r"(bytes), "r"(mbar) : "memory");
}
__device__ __forceinline__ void bulk_s2g(void* g, unsigned saddr, unsigned bytes) {
    asm volatile("cp.async.bulk.global.shared::cta.bulk_group [%0], [%1], %2;"
        :: "l"(g), "r"(saddr), "r"(bytes) : "memory");
}
__device__ __forceinline__ void bulk_commit() {
    asm volatile("cp.async.bulk.commit_group;" ::: "memory");
}
template <int N>
__device__ __forceinline__ void bulk_wait() {
    asm volatile("cp.async.bulk.wait_group %0;" :: "n"(N) : "memory");
}

// Coalesced matvec via blocked-transposed weights; vec from smem.
__device__ __forceinline__ float matvec_bt(const ulonglong2* __restrict__ BT2, int h,
                                           const float* __restrict__ vec) {
    const ulonglong2* v = (const ulonglong2*)vec;
    unsigned long long acc = 0ull;
    #pragma unroll
    for (int b = 0; b < 4; ++b) {
        ulonglong2 w[16];
        #pragma unroll
        for (int i = 0; i < 16; ++i) w[i] = BT2[(b * 16 + i) * H + h];
        #pragma unroll
        for (int i = 0; i < 16; ++i) {
            fma2(acc, w[i].x, v[b * 16 + i].x);
            fma2(acc, w[i].y, v[b * 16 + i].y);
        }
    }
    float lo, hi; upk2(acc, lo, hi);
    return lo + hi;
}

// ------------------------------- kernels -----------------------------------
// Merged clear + weight transpose. 65536 threads.
__global__ void k_prep(const float* __restrict__ Wh,  const float* __restrict__ We2n,
                       const float* __restrict__ Wre, const float* __restrict__ Wrn) {
    int idx = blockIdx.x * blockDim.x + threadIdx.x;
    if (idx < HSIZE) { g_hrow[idx] = -1; g_hcnt[idx] = 0; }
    if (idx < BDIM) { g_done[idx] = 0; g_needed[idx] = 0; }
    if (idx == 0) g_ctr = 0;
    int m = idx >> 14, rem = idx & 16383;
    int i4 = rem >> 8, h = rem & 255;
    const float* W = (m == 0) ? Wh : (m == 1) ? We2n : (m == 2) ? Wre : Wrn;
    g_BT[m][i4 * H + h] = *(const float4*)(W + (size_t)h * H + i4 * 4);
}

__global__ void k_insert(const int* __restrict__ u) {
    int idx = blockIdx.x * blockDim.x + threadIdx.x;
    if (idx >= BDIM * NSLOT) return;
    int t = idx / NSLOT, w = idx % NSLOT;
    int row = u[t * NSLOT + w];
    int prio = (w == 0) ? 16 : (w - 1);            // event applied last; later neighbor wins
    int e = (t << 10) | (prio << 5) | w;
    unsigned hsh = hashrow(row);
    for (;;) {
        int cur = atomicCAS(&g_hrow[hsh], -1, row);
        if (cur == -1 || cur == row) {
            int c = atomicAdd(&g_hcnt[hsh], 1);
            if (c < HK) g_hent[hsh][c] = e;
            break;
        }
        hsh = (hsh + 1) & HMASK;
    }
}

__global__ void k_resolve(const int* __restrict__ u, const int* __restrict__ u_neg,
                          const float* __restrict__ z0, const float* __restrict__ time_bar,
                          const float* __restrict__ td) {
    int idx = blockIdx.x * blockDim.x + threadIdx.x;
    if (idx < 1088) prefetch_l2(td + idx * 32);    // whole td array
    if (idx >= BDIM * NREAD) return;
    int t = idx / NREAD, r = idx % NREAD;
    int row = (r < NSLOT) ? u[t * NSLOT + r] : u_neg[t * NEGK + (r - NSLOT)];
    if (r >= NSLOT) prefetch_l2(time_bar + (size_t)t * NNODES + row);
    unsigned hsh = hashrow(row);
    int src = -1, bestkey = -1;
    for (;;) {
        int cur = g_hrow[hsh];
        if (cur == -1) break;
        if (cur == row) {
            int c = g_hcnt[hsh]; if (c > HK) c = HK;
            for (int i = 0; i < c; ++i) {
                int e = g_hent[hsh][i];
                if ((e >> 10) < t) {
                    int key = e >> 5;
                    if (key > bestkey) { bestkey = key; src = ((e >> 10) << 5) | (e & 31); }
                }
            }
            break;
        }
        hsh = (hsh + 1) & HMASK;
    }
    g_src[t][r] = src;
    if (src >= 0) {
        if (r < NSLOT) atomicOr(&g_needed[src >> 5], 1 << (src & 31));
    } else {
        const float* p = z0 + (size_t)row * H;     // prefetch the z0 row
        #pragma unroll
        for (int l = 0; l < 8; ++l) prefetch_l2(p + l * 32);
    }
}

// Persistent main kernel: 256 threads/CTA, 2 CTAs/SM, single work counter.
// ids [0,512): solo steps. [512,...): copy chunks with 4 parallel TMA streams.
__global__ void __launch_bounds__(NTHR, 2) k_main(
    const int* __restrict__ u, const float* __restrict__ td,
    const float* __restrict__ z0,
    const float* __restrict__ bh,  const float* __restrict__ be2n,
    const float* __restrict__ bre, const float* __restrict__ brn,
    const float* __restrict__ Wt,  const float* __restrict__ bt,
    float* __restrict__ out)
{
    __shared__ __align__(16) float s_znb[DEG][H];
    __shared__ __align__(16) float s_emb[H];
    __shared__ __align__(16) float s_mean[H];
    __shared__ float s_td[NSLOT][4];
    __shared__ __align__(8) unsigned long long s_mbar[NSTREAM * NBUFS];
    __shared__ int s_id;
    extern __shared__ __align__(16) char s_buf[];        // NSTREAM*NBUFS x 6KB buffers

    const int tid  = threadIdx.x;              // == h (output column)
    const int lane = tid & 31, wid = tid >> 5;
    char* outzb = (char*)(out + (BDIM + BDIM * NEGK));
    const ulonglong2* BT_h   = (const ulonglong2*)g_BT[0];
    const ulonglong2* BT_e2n = (const ulonglong2*)g_BT[1];
    const ulonglong2* BT_re  = (const ulonglong2*)g_BT[2];
    const ulonglong2* BT_rn  = (const ulonglong2*)g_BT[3];
    const float inv_sd[4] = {1.f/50.f, 1.f/7.f, 1.f/15.f, 1.f/15.f};

    // TMA copy state: stream thread = lane 0 of warps 0..3; stream id = wid.
    unsigned sbase = (unsigned)__cvta_generic_to_shared(s_buf);
    unsigned mbase = (unsigned)__cvta_generic_to_shared(&s_mbar[0]);
    unsigned phs[NBUFS] = {0, 0, 0};           // per-stream-thread buffer phases
    if (tid == 0) {
        #pragma unroll
        for (int i = 0; i < NSTREAM * NBUFS; ++i) mbar_init(mbase + i * 8, 1);
    }

    for (;;) {
        __syncthreads();                      // protect s_id / smem; orders mbar init
        if (tid == 0) s_id = atomicAdd(&g_ctr, 1);
        __syncthreads();
        const int id = s_id;
        if (id >= TOTAL_WORK) break;

        // =================== COPY CHUNK: 4 parallel TMA streams ===================
        if (id >= BDIM) {
            if (wid < NSTREAM && lane == 0) {
                const int st = wid;
                int chunk = id - BDIM;
                size_t byte0 = (size_t)chunk * (CPR * H * 4);
                size_t total = (size_t)NNODES * H * 4;
                size_t rem = total - byte0;
                unsigned nb = (unsigned)((rem < (size_t)(CPR * H * 4)) ? rem
                                                                       : (size_t)(CPR * H * 4));
                const char* src = (const char*)z0 + byte0;
                char*       dst = outzb + byte0;
                unsigned ntile = (nb + TILE - 1) / TILE;       // 43 (last chunk: 11)
                // stream st owns tiles st, st+4, st+8, ...
                // prime 2 loads (local k = 0, 1)
                #pragma unroll
                for (unsigned kk = 0; kk < 2; ++kk) {
                    unsigned t = st + kk * NSTREAM;
                    if (t < ntile) {
                        unsigned b = st * NBUFS + kk;
                        unsigned tb = ((t + 1) * TILE <= nb) ? TILE : (nb - t * TILE);
                        mbar_expect(mbase + b * 8, tb);
                        bulk_g2s(sbase + b * TILE, src + (size_t)t * TILE, tb, mbase + b * 8);
                    }
                }
                unsigned k = 0;
                for (unsigned t = st; t < ntile; t += NSTREAM, ++k) {
                    unsigned bi = k % NBUFS;
                    unsigned b = st * NBUFS + bi;
                    unsigned tb = ((t + 1) * TILE <= nb) ? TILE : (nb - t * TILE);
                    mbar_wait(mbase + b * 8, phs[bi]); phs[bi] ^= 1;
                    bulk_s2g(dst + (size_t)t * TILE, sbase + b * TILE, tb);
                    bulk_commit();
                    bulk_wait<1>();            // store k-1 done -> its buffer free
                    unsigned tn = t + 2 * NSTREAM;     // load local k+2
                    if (tn < ntile) {
                        unsigned bn = st * NBUFS + ((k + 2) % NBUFS);
                        unsigned tbn = ((tn + 1) * TILE <= nb) ? TILE : (nb - tn * TILE);
                        mbar_expect(mbase + bn * 8, tbn);
                        bulk_g2s(sbase + bn * TILE, src + (size_t)tn * TILE, tbn,
                                 mbase + bn * 8);
                    }
                }
                bulk_wait<0>();                // drain before buffers reused next chunk
            }
            continue;
        }

        // =================== STEP s ===================
        const int s = id;

        // ---- Phase 0: warp 0 waits on dependent slots; warps 1..7 load
        //      independent (z0-sourced) rows concurrently ----
        if (wid == 0) {
            if (lane < NSLOT) {
                int sv = g_src[s][lane];
                if (sv >= 0) wait_bit(&g_done[sv >> 5], 1 << (sv & 31));
            }
        } else {
            for (int r = wid - 1; r < NSLOT; r += 7) {
                int sv = g_src[s][r];
                if (sv < 0) {
                    const float4* src4 = (const float4*)(z0 + (size_t)u[s * NSLOT + r] * H);
                    float4* dst4 = (r == 0) ? (float4*)s_emb : (float4*)s_znb[r - 1];
                    dst4[lane]      = src4[lane];
                    dst4[lane + 32] = src4[lane + 32];
                }
            }
        }
        __syncthreads();

        // ---- Phase 0b: load dependent rows (usually 0-2) + time deltas ----
        for (int r = wid; r < NSLOT; r += 8) {
            int sv = g_src[s][r];
            if (sv >= 0) {
                const float4* src4 = (const float4*)g_staging[sv >> 5][sv & 31];
                float4* dst4 = (r == 0) ? (float4*)s_emb : (float4*)s_znb[r - 1];
                dst4[lane]      = src4[lane];
                dst4[lane + 32] = src4[lane + 32];
            }
        }
        if (tid >= 188) {                       // 68 threads load 68 td values
            int q = tid - 188;
            s_td[q >> 2][q & 3] = td[(s * NSLOT + (q >> 2)) * 4 + (q & 3)] * inv_sd[q & 3];
        }
        __syncthreads();

        const int h = tid;
        const int need = g_needed[s];
        const int nneed = (need >> 1) & 0xFFFF;    // needed neighbor slots
        float4 wtr = *(const float4*)(Wt + (size_t)h * 4);
        float btv = bt[h];

        // cmn first (needs only emb) — prerequisite of every neighbor row
        float cmn = matvec_bt(BT_e2n, h, s_emb) + be2n[h] + brn[h];

        // ---- Phase 1a: publish needed NEIGHBOR slots (no mean required) ----
        if (nneed) {
            for (int m = nneed; m; m &= (m - 1)) {
                int j = __ffs(m) - 1;
                float d = matvec_bt(BT_rn, h, s_znb[j]);
                float tf = btv + wtr.x*s_td[1+j][0] + wtr.y*s_td[1+j][1]
                               + wtr.z*s_td[1+j][2] + wtr.w*s_td[1+j][3];
                g_staging[s][1 + j][h] = sigmoidf_(d + cmn + tf);
            }
            __syncthreads();
            if (tid == 0) red_or_rel(&g_done[s], nneed << 1);
        }

        // ---- mean over 16 neighbor rows (only z_ev needs it) ----
        {
            float acc = 0.f;
            #pragma unroll
            for (int j = 0; j < DEG; ++j) acc += s_znb[j][tid];
            s_mean[tid] = acc * (1.0f / DEG);
        }
        __syncthreads();

        // ---- Phase 1b: z_ev; publish early iff someone reads it ----
        {
            float ah = matvec_bt(BT_h,  h, s_mean);
            float ae = matvec_bt(BT_re, h, s_emb);
            float tf0 = btv + wtr.x*s_td[0][0] + wtr.y*s_td[0][1]
                            + wtr.z*s_td[0][2] + wtr.w*s_td[0][3];
            g_staging[s][0][h] = sigmoidf_(ah + bh[h] + ae + bre[h] + tf0);
            if (need & 1) {
                __syncthreads();
                if (tid == 0) red_or_rel(&g_done[s], 1);
            }
        }

        // ---- Phase 2: remaining neighbor slots (GEMM, 4-deep weight prefetch) ----
        {
            unsigned long long acc2[DEG];
            #pragma unroll
            for (int j = 0; j < DEG; ++j) acc2[j] = 0ull;
            ulonglong2 wb[4];
            #pragma unroll
            for (int p = 0; p < 4; ++p) wb[p] = BT_rn[p * H + h];
            for (int i4 = 0; i4 < H / 4; i4 += 4) {
                ulonglong2 w0 = wb[0], w1 = wb[1], w2 = wb[2], w3 = wb[3];
                if (i4 + 4 < H / 4) {
                    #pragma unroll
                    for (int p = 0; p < 4; ++p) wb[p] = BT_rn[(i4 + 4 + p) * H + h];
                }
                #pragma unroll
                for (int j = 0; j < DEG; ++j) {
                    ulonglong2 z0v = *(const ulonglong2*)&s_znb[j][i4 * 4];
                    fma2(acc2[j], w0.x, z0v.x); fma2(acc2[j], w0.y, z0v.y);
                    ulonglong2 z1v = *(const ulonglong2*)&s_znb[j][(i4 + 1) * 4];
                    fma2(acc2[j], w1.x, z1v.x); fma2(acc2[j], w1.y, z1v.y);
                    ulonglong2 z2v = *(const ulonglong2*)&s_znb[j][(i4 + 2) * 4];
                    fma2(acc2[j], w2.x, z2v.x); fma2(acc2[j], w2.y, z2v.y);
                    ulonglong2 z3v = *(const ulonglong2*)&s_znb[j][(i4 + 3) * 4];
                    fma2(acc2[j], w3.x, z3v.x); fma2(acc2[j], w3.y, z3v.y);
                }
            }
            #pragma unroll
            for (int j = 0; j < DEG; ++j) {
                if (!((nneed >> j) & 1)) {
                    float lo, hi; upk2(acc2[j], lo, hi);
                    float tf = btv + wtr.x*s_td[1+j][0] + wtr.y*s_td[1+j][1]
                                   + wtr.z*s_td[1+j][2] + wtr.w*s_td[1+j][3];
                    g_staging[s][1 + j][h] = sigmoidf_(lo + hi + cmn + tf);
                }
            }
        }
        __syncthreads();
        if (tid == 0) red_or_rel(&g_done[s], FULLMASK);
    }
}

// Post pass: one block per step. Hawkes lambdas (pos + 5 neg) and final scatter
// of last-writer rows over the copied z0 region. Runs after k_main completes.
__global__ void __launch_bounds__(NTHR) k_post(
    const int* __restrict__ u, const int* __restrict__ u_neg,
    const float* __restrict__ time_bar, const float* __restrict__ time_cur,
    const float* __restrict__ td, const float* __restrict__ z0,
    const float* __restrict__ Wom, const float* __restrict__ bom_p,
    const float* __restrict__ wt_p, const float* __restrict__ alpha_p,
    const float* __restrict__ psi_p, float* __restrict__ out)
{
    const int s = blockIdx.x;
    const int tid = threadIdx.x, lane = tid & 31, wid = tid >> 5;
    const float w_t = *wt_p, alpha = *alpha_p, psi = *psi_p, bom = *bom_p;
    const float inv_psi = 1.0f / (psi + 1e-7f);
    float* outz = out + (BDIM + BDIM * NEGK);

    if (wid < NEGK) {                            // negative lambdas
        int node = u_neg[s * NEGK + wid];
        int sv = g_src[s][NSLOT + wid];
        const float* srcp = (sv >= 0) ? g_staging[sv >> 5][sv & 31]
                                      : (z0 + (size_t)node * H);
        float acc = 0.f;
        for (int i = lane; i < H; i += 32) acc += srcp[i] * Wom[i];
        #pragma unroll
        for (int o = 16; o; o >>= 1) acc += __shfl_down_sync(0xffffffffu, acc, o);
        if (lane == 0) {
            float ts = time_cur[s] - time_bar[(size_t)s * NNODES + node];
            float g = acc + bom + alpha * expf(-w_t * (ts * (1.0f / 86400.0f)));
            float gp = fminf(fmaxf(g * inv_psi, -75.f), 75.f);
            out[BDIM + s * NEGK + wid] = psi * log1pf(expf(gp)) * (1.0f / NEGK);
        }
    } else if (wid == 5) {                       // positive lambda
        int sv = g_src[s][0];
        const float* srcp = (sv >= 0) ? g_staging[sv >> 5][sv & 31]
                                      : (z0 + (size_t)u[s * NSLOT] * H);
        float acc = 0.f;
        for (int i = lane; i < H; i += 32) acc += srcp[i] * Wom[i];
        #pragma unroll
        for (int o = 16; o; o >>= 1) acc += __shfl_down_sync(0xffffffffu, acc, o);
        if (lane == 0) {
            float ts = time_cur[s] - td[s * NSLOT * 4] * (1.0f / 50.0f);
            float g = acc + bom + alpha * expf(-w_t * (ts * (1.0f / 86400.0f)));
            float gp = fminf(fmaxf(g * inv_psi, -75.f), 75.f);
            out[s] = psi * log1pf(expf(gp));
        }
    }

    // scatter: warp handles slots wid, wid+8, wid+16
    for (int w = wid; w < NSLOT; w += 8) {
        int row = u[s * NSLOT + w];
        unsigned hsh = hashrow(row);
        int beste = -1, bestkey = -1;
        for (;;) {
            int cur = g_hrow[hsh];
            if (cur == -1) break;
            if (cur == row) {
                int c = g_hcnt[hsh]; if (c > HK) c = HK;
                for (int i = 0; i < c; ++i) {
                    int e = g_hent[hsh][i];
                    int key = e >> 5;
                    if (key > bestkey) { bestkey = key; beste = e; }
                }
                break;
            }
            hsh = (hsh + 1) & HMASK;
        }
        int prio = (w == 0) ? 16 : (w - 1);
        if (beste == ((s << 10) | (prio << 5) | w)) {   // this (s,w) is the last writer
            const float4* src = (const float4*)g_staging[s][w];
            float4* dst = (float4*)outz + (size_t)row * (H / 4);
            dst[lane]      = src[lane];
            dst[lane + 32] = src[lane + 32];
        }
    }
}

// ------------------------------- launch ------------------------------------
extern "C" void kernel_launch(void* const* d_in, const int* in_sizes, int n_in,
                              void* d_out, int out_size) {
    const int*   u     = (const int*)  d_in[0];
    const float* td    = (const float*)d_in[1];
    const float* tbar  = (const float*)d_in[2];
    const float* tcur  = (const float*)d_in[3];
    // d_in[4] significance, d_in[5] magnitudo: unused by reference
    const int*   uneg  = (const int*)  d_in[6];
    const float* z0    = (const float*)d_in[7];
    const float* Wh    = (const float*)d_in[8];
    const float* bh    = (const float*)d_in[9];
    const float* We2n  = (const float*)d_in[10];
    const float* be2n  = (const float*)d_in[11];
    const float* Wre   = (const float*)d_in[12];
    const float* bre   = (const float*)d_in[13];
    const float* Wrn   = (const float*)d_in[14];
    const float* brn   = (const float*)d_in[15];
    const float* Wt    = (const float*)d_in[16];
    const float* bt    = (const float*)d_in[17];
    const float* Wom   = (const float*)d_in[18];
    const float* bom   = (const float*)d_in[19];
    const float* wt    = (const float*)d_in[20];
    const float* alpha = (const float*)d_in[21];
    const float* psi   = (const float*)d_in[22];
    float* out = (float*)d_out;

    static int attr_set = 0;
    if (!attr_set) {
        cudaFuncSetAttribute(k_main, cudaFuncAttributeMaxDynamicSharedMemorySize, DSMEM);
        attr_set = 1;
    }

    k_prep   <<<256, 256>>>(Wh, We2n, Wre, Wrn);
    k_insert <<<(BDIM * NSLOT + 255) / 256, 256>>>(u);
    k_resolve<<<(BDIM * NREAD + 255) / 256, 256>>>(u, uneg, z0, tbar, td);

    int dev = 0, nsm = 148;
    cudaGetDevice(&dev);
    cudaDeviceGetAttribute(&nsm, cudaDevAttrMultiProcessorCount, dev);

    k_main<<<nsm * 2, NTHR, DSMEM>>>(u, td, z0, bh, be2n, bre, brn, Wt, bt, out);

    k_post<<<BDIM, NTHR>>>(u, uneg, tbar, tcur, td, z0,
                           Wom, bom, wt, alpha, psi, out);
}